// round 11
// baseline (speedup 1.0000x reference)
#include <cuda_runtime.h>

// ---------------- problem constants ----------------
#define TB 64           // batch
#define TT 1024         // time steps
#define TI 64           // input size
#define TH 256          // hidden size
#define NGROUP 4        // independent batch groups
#define CPG 32          // CTAs per group
#define BPG 16          // batches per group
#define NCTA (NGROUP*CPG)
#define NTHR 256
#define K0 320          // layer0 concat [x(64) ; h0_d(256)]
#define K1 768          // layer1 concat [h0cat(512) ; h1_d(256)]
#define BP  17          // gates buffer batch stride

// smem partition (floats)
#define OFS_SW0 0
#define OFS_SW1 (48*K0)                       // 15360
#define OFS_SX  (OFS_SW1 + 48*K1)             // 52224 : 2 buffers [16][128] unpadded
#define OFS_GA  (OFS_SX + 2*2048)             // 56320 : [48 rows][BP]
#define OFS_GB  (OFS_GA + 48*BP)              // 57136 : [16][BP]
#define OFS_MBAR (OFS_GB + 16*BP)             // 57408 : 2 mbarriers (4 floats)
#define SMEM_FLOATS (OFS_MBAR + 4)            // 57412 floats = 229648 bytes

// ---------------- device scratch ----------------
__device__ float g_xT[TT * TB * TI];          // [t][b][i] : per-group slice contiguous (4KB)
// h layout: [parity][chunk(u>>7)][b][u&127] -> every (chunk, 16-batch) slab is 8KB contiguous
__device__ float g_h0[2 * 4 * TB * 128];
__device__ float g_h1[2 * 4 * TB * 128];
__device__ int      g_barA_count[NGROUP];     // barrier A : h0 publish
__device__ unsigned g_barA_gen[NGROUP];
__device__ int      g_barB_count[NGROUP];     // barrier B : h1 publish
__device__ unsigned g_barB_gen[NGROUP];

// ---------------- input transpose ----------------
__global__ void transpose_kernel(const float* __restrict__ x) {
    int idx = blockIdx.x * blockDim.x + threadIdx.x;
    if (idx < TT * TB * TI) {
        int i = idx & 63;
        int b = (idx >> 6) & 63;
        int t = idx >> 12;
        g_xT[idx] = x[(b * TT + t) * TI + i];
    }
}

__device__ __forceinline__ float sigmf(float v) { return 1.0f / (1.0f + __expf(-v)); }
__device__ __forceinline__ float tanh_fast(float v) { return 2.0f / (1.0f + __expf(-2.0f * v)) - 1.0f; }

__device__ __forceinline__ void fma2(unsigned long long& acc,
                                     unsigned long long a, unsigned long long b) {
    asm("fma.rn.f32x2 %0, %1, %2, %0;" : "+l"(acc) : "l"(a), "l"(b));
}

// ---------------- mbarrier + TMA bulk helpers ----------------
__device__ __forceinline__ void mbar_init(unsigned mbar) {
    asm volatile("mbarrier.init.shared.b64 [%0], 1;" :: "r"(mbar) : "memory");
}
__device__ __forceinline__ void mwait(unsigned mbar, int parity) {
    asm volatile(
        "{\n\t.reg .pred P;\n\t"
        "WAIT_%=:\n\t"
        "mbarrier.try_wait.parity.acquire.cta.shared::cta.b64 P, [%0], %1, 0x989680;\n\t"
        "@P bra DONE_%=;\n\t"
        "bra WAIT_%=;\n\t"
        "DONE_%=:\n\t}"
        :: "r"(mbar), "r"(parity) : "memory");
}
// one elected thread: expect_tx + 1D bulk copy gmem->smem
__device__ __forceinline__ void stage_bulk(unsigned sdst, const float* gsrc,
                                           unsigned bytes, unsigned mbar) {
    if (threadIdx.x == 0) {
        asm volatile("mbarrier.arrive.expect_tx.shared.b64 _, [%0], %1;"
                     :: "r"(mbar), "r"(bytes) : "memory");
        asm volatile("cp.async.bulk.shared::cta.global.mbarrier::complete_tx::bytes [%0], [%1], %2, [%3];"
                     :: "r"(sdst), "l"(gsrc), "r"(bytes), "r"(mbar) : "memory");
    }
}

// ---------------- split group barriers (proven atomic primitives) ----------------
__device__ __forceinline__ void bar_arrive(int* cnt, unsigned* gen, int grp) {
    __syncthreads();                          // all threads' global stores issued
    if (threadIdx.x == 0) {
        __threadfence();                      // release
        int prev = atomicAdd(&cnt[grp], 1);
        if (prev == CPG - 1) {
            atomicExch(&cnt[grp], 0);
            __threadfence();
            atomicAdd(&gen[grp], 1u);
        }
    }
}
__device__ __forceinline__ void bar_wait(unsigned* gen, int grp, unsigned target) {
    if (threadIdx.x == 0) {
        while (atomicAdd(&gen[grp], 0u) < target) { }
        __threadfence();                      // acquire
    }
    __syncthreads();
}

// split-K register-tiled accumulation; XS = smem row stride (floats).
// lane: ks = lane & 15, c = lane >> 4.  One j-iter covers 64 consecutive k.
template <int ITERS, int XS>
__device__ __forceinline__ void accum_chunk(unsigned long long acc[6][8],
                                            const float* __restrict__ wbase, int K,
                                            const float* __restrict__ sx,
                                            int ks, int c) {
    const float* xb = sx + (c * 8) * XS;
#pragma unroll
    for (int j = 0; j < ITERS; ++j) {
        int k4 = (j * 16 + ks) * 4;
        ulonglong2 xv[8];
#pragma unroll
        for (int i = 0; i < 8; ++i)
            xv[i] = *reinterpret_cast<const ulonglong2*>(xb + i * XS + k4);
        ulonglong2 wv[6];
#pragma unroll
        for (int r = 0; r < 6; ++r)
            wv[r] = *reinterpret_cast<const ulonglong2*>(wbase + r * K + k4);
#pragma unroll
        for (int r = 0; r < 6; ++r)
#pragma unroll
            for (int i = 0; i < 8; ++i) {
                fma2(acc[r][i], wv[r].x, xv[i].x);
                fma2(acc[r][i], wv[r].y, xv[i].y);
            }
    }
}

// fold n-rows (4,5) into sv and reset them (r/z rows keep running)
__device__ __forceinline__ void fold_n(unsigned long long acc[6][8], float sv[2][8]) {
#pragma unroll
    for (int q = 0; q < 2; ++q)
#pragma unroll
        for (int i = 0; i < 8; ++i) {
            union { unsigned long long u; float2 f; } cv; cv.u = acc[4 + q][i];
            sv[q][i] = cv.f.x + cv.f.y;
            acc[4 + q][i] = 0ull;
        }
}

// end-of-layer reduce. SAVED_IS_I: true -> sv is the n-gate INPUT part (layer0),
// false -> sv is the n-gate HIDDEN part (layer1, B4/B5 computed first).
template <bool SAVED_IS_I>
__device__ __forceinline__ void reduce_layer(unsigned long long acc[6][8],
                                             const float sv[2][8],
                                             int w, int lane,
                                             float* __restrict__ GA, float* __restrict__ GB) {
    const int c = lane >> 4;
    const bool wr = (lane & 15) == 0;
#pragma unroll
    for (int q = 0; q < 4; ++q) {              // r/z rows (total only)
        int garow = w * 4 + q;
#pragma unroll
        for (int i = 0; i < 8; ++i) {
            union { unsigned long long u; float2 f; } cv; cv.u = acc[q][i];
            float s = cv.f.x + cv.f.y;
            acc[q][i] = 0ull;
            s += __shfl_xor_sync(0xffffffffu, s, 1);
            s += __shfl_xor_sync(0xffffffffu, s, 2);
            s += __shfl_xor_sync(0xffffffffu, s, 4);
            s += __shfl_xor_sync(0xffffffffu, s, 8);
            if (wr) GA[garow * BP + c * 8 + i] = s;
        }
    }
#pragma unroll
    for (int q = 0; q < 2; ++q) {              // n rows
        int nn = w * 2 + q;
#pragma unroll
        for (int i = 0; i < 8; ++i) {
            union { unsigned long long u; float2 f; } cv; cv.u = acc[4 + q][i];
            float a = cv.f.x + cv.f.y;         // live accumulator part
            acc[4 + q][i] = 0ull;
            a += __shfl_xor_sync(0xffffffffu, a, 1);
            a += __shfl_xor_sync(0xffffffffu, a, 2);
            a += __shfl_xor_sync(0xffffffffu, a, 4);
            a += __shfl_xor_sync(0xffffffffu, a, 8);
            float s = sv[q][i];                // saved part
            s += __shfl_xor_sync(0xffffffffu, s, 1);
            s += __shfl_xor_sync(0xffffffffu, s, 2);
            s += __shfl_xor_sync(0xffffffffu, s, 4);
            s += __shfl_xor_sync(0xffffffffu, s, 8);
            if (wr) {
                if (SAVED_IS_I) {              // layer0: saved=I, rows=H
                    GA[(32 + nn) * BP + c * 8 + i] = s;
                    GB[nn * BP + c * 8 + i] = a;
                } else {                       // layer1: rows=I, saved=H
                    GA[(32 + nn) * BP + c * 8 + i] = a;
                    GB[nn * BP + c * 8 + i] = s;
                }
            }
        }
    }
}

// ---------------- persistent GRU kernel ----------------
__global__ void __launch_bounds__(NTHR, 1) gru_persistent(
    const float* __restrict__ W_ih0, const float* __restrict__ W_hh0,
    const float* __restrict__ b_ih0, const float* __restrict__ b_hh0,
    const float* __restrict__ W_ih1, const float* __restrict__ W_hh1,
    const float* __restrict__ b_ih1, const float* __restrict__ b_hh1,
    const int* __restrict__ seq_len, float* __restrict__ out)
{
    extern __shared__ float smem[];
    float* sw0 = smem + OFS_SW0;   // [48 warp-major rows][K0]
    float* sw1 = smem + OFS_SW1;   // [48][K1]
    float* fx0 = smem + OFS_SX;            // physical buffer 0 : [16][128]
    float* fx1 = smem + OFS_SX + 2048;     // physical buffer 1
    float* GA  = smem + OFS_GA;    // [48][BP]  rows: r(0-15), z(16-31), nI(32-47)
    float* GB  = smem + OFS_GB;    // [16][BP]  nH

    const unsigned smem_u32 = (unsigned)__cvta_generic_to_shared(smem);
    const unsigned sx0_u = smem_u32 + OFS_SX * 4;
    const unsigned sx1_u = sx0_u + 2048 * 4;
    const unsigned mb0_u = smem_u32 + OFS_MBAR * 4;
    const unsigned mb1_u = mb0_u + 8;

    const int tid = threadIdx.x;
    const int cta = blockIdx.x;
    const int grp = cta / CPG;
    const int cg  = cta % CPG;
    const int d     = cg >> 4;
    const int jbase = (cg & 15) * 16;
    const int gb    = grp * BPG;

    const int warp = tid >> 5;
    const int lane = tid & 31;
    const int ks   = lane & 15;
    const int c    = lane >> 4;

    const int lu = tid & 15;
    const int b  = tid >> 4;
    const int j  = jbase + lu;
    const int u  = d * TH + j;
    // h index: [parity][u>>7][gb+b][u&127]
    const int me_h = (u >> 7) * (TB * 128) + (gb + b) * 128 + (u & 127);

    // ---- init mbarriers ----
    if (tid == 0) { mbar_init(mb0_u); mbar_init(mb1_u); }
    asm volatile("fence.proxy.async.shared::cta;" ::: "memory");
    __syncthreads();

    // ---- stage weights into smem (warp-major rows: 4 r/z + 2 n per warp) ----
    for (int idx = tid; idx < 48 * K0; idx += NTHR) {
        int k = idx % K0, sr = idx / K0;
        int w = sr / 6, q = sr % 6;
        int gu;
        if (q < 4) { int rz = w * 4 + q; gu = (rz >> 4) * 256 + jbase + (rz & 15); }
        else       { int nn = w * 2 + (q - 4); gu = 512 + jbase + nn; }
        int grow = d * 768 + gu;
        sw0[idx] = (k < TI) ? W_ih0[grow * TI + k] : W_hh0[grow * TH + (k - TI)];
    }
    for (int idx = tid; idx < 48 * K1; idx += NTHR) {
        int k = idx % K1, sr = idx / K1;
        int w = sr / 6, q = sr % 6;
        int gu;
        if (q < 4) { int rz = w * 4 + q; gu = (rz >> 4) * 256 + jbase + (rz & 15); }
        else       { int nn = w * 2 + (q - 4); gu = 512 + jbase + nn; }
        int grow = d * 768 + gu;
        sw1[idx] = (k < 512) ? W_ih1[grow * 512 + k] : W_hh1[grow * TH + (k - 512)];
    }

    const int base = d * 768;
    const float b0r = b_ih0[base + j] + b_hh0[base + j];
    const float b0z = b_ih0[base + TH + j] + b_hh0[base + TH + j];
    const float b0ni = b_ih0[base + 2 * TH + j];
    const float b0nh = b_hh0[base + 2 * TH + j];
    const float b1r = b_ih1[base + j] + b_hh1[base + j];
    const float b1z = b_ih1[base + TH + j] + b_hh1[base + TH + j];
    const float b1ni = b_ih1[base + 2 * TH + j];
    const float b1nh = b_hh1[base + 2 * TH + j];

    int myidx = seq_len[gb + b] - 1;
    if (myidx < 0) myidx = 0;
    if (myidx > TT - 1) myidx = TT - 1;

    // zero initial hidden state (parity 0)
    __stcg(&g_h0[me_h], 0.0f);
    __stcg(&g_h1[me_h], 0.0f);

    __shared__ unsigned s_genA, s_genB;
    if (tid == 0) {
        s_genA = atomicAdd(&g_barA_gen[grp], 0u);
        s_genB = atomicAdd(&g_barB_gen[grp], 0u);
    }
    __syncthreads();
    const unsigned genA = s_genA;
    const unsigned genB = s_genB;

    // prologue: barB arrive represents "h1(-1) zeros published";
    // barA full barrier makes h0 zeros (and everything else) visible group-wide.
    bar_arrive(g_barB_count, g_barB_gen, grp);
    bar_arrive(g_barA_count, g_barA_gen, grp);
    bar_wait(g_barA_gen, grp, genA + 1);

    unsigned long long acc[6][8];
#pragma unroll
    for (int r = 0; r < 6; ++r)
#pragma unroll
        for (int i = 0; i < 8; ++i) acc[r][i] = 0ull;

    const float* sw0w = sw0 + warp * 6 * K0;
    const float* sw1w = sw1 + warp * 6 * K1;

    // role-tracked buffer state (swapped each step; stays in registers)
    float*   Xf = fx0;  float*   Yf = fx1;
    unsigned Xu = sx0_u; unsigned Yu = sx1_u;
    unsigned Xm = mb0_u; unsigned Ym = mb1_u;
    int phX = 0, phY = 0;

    // prologue staging: A0(0) -> X, A1(0) -> Y
    stage_bulk(Xu, g_xT + gb * TI, 4096, Xm);
    stage_bulk(Yu, g_h0 + (2 * d) * (TB * 128) + gb * 128, 8192, Ym);

    for (int t = 0; t < TT; ++t) {
        const int rp = t & 1, wp = rp ^ 1;
        const float* h0r = g_h0 + rp * (4 * TB * 128);
        float*       h0w = g_h0 + wp * (4 * TB * 128);
        const float* h1r = g_h1 + rp * (4 * TB * 128);
        float*       h1w = g_h1 + wp * (4 * TB * 128);

        float sv[2][8];

        // ================= phase 1 : layer 0 =================
        float hp0 = __ldcg(h0r + me_h);    // own thread's prior write
        float hp1 = __ldcg(h1r + me_h);    // own thread's prior write

        // A0 (X): x part, stride 64
        mwait(Xm, phX & 1); phX++;
        accum_chunk<1, 64>(acc, sw0w, K0, Xf, ks, c);
        fold_n(acc, sv);                                    // sv = nI (layer0)
        __syncthreads();
        stage_bulk(Xu, h0r + (2 * d + 1) * (TB * 128) + gb * 128, 8192, Xm);  // A2
        // A1 (Y): h0_d chunk 2d
        mwait(Ym, phY & 1); phY++;
        accum_chunk<2, 128>(acc, sw0w + TI, K0, Yf, ks, c);
        // A2 (X): h0_d chunk 2d+1
        mwait(Xm, phX & 1); phX++;
        accum_chunk<2, 128>(acc, sw0w + TI + 128, K0, Xf, ks, c);
        reduce_layer<true>(acc, sv, warp, lane, GA, GB);
        __syncthreads();
        {
            float aR  = GA[lu * BP + b] + b0r;
            float aZ  = GA[(16 + lu) * BP + b] + b0z;
            float aI  = GA[(32 + lu) * BP + b] + b0ni;
            float aH  = GB[lu * BP + b] + b0nh;
            float r  = sigmf(aR);
            float z  = sigmf(aZ);
            float n  = tanh_fast(aI + r * aH);
            float hn = n + z * (hp0 - n);
            __stcg(h0w + me_h, hn);
        }

        // publish h0(t); its wait is deferred past the h1-hidden part
        bar_arrive(g_barA_count, g_barA_gen, grp);

        // h1(t-1) must be globally published before B4/B5 read it.
        // barB was arrived at the END of step t-1 (prologue for t=0), and the
        // whole phase 1 has covered its latency.
        bar_wait(g_barB_gen, grp, genB + 1 + (unsigned)t);

        // B4 (Y), B5 (X): h1_d chunks
        stage_bulk(Yu, h1r + (2 * d) * (TB * 128) + gb * 128, 8192, Ym);
        stage_bulk(Xu, h1r + (2 * d + 1) * (TB * 128) + gb * 128, 8192, Xm);
        mwait(Ym, phY & 1); phY++;
        accum_chunk<2, 128>(acc, sw1w + 512, K1, Yf, ks, c);   // n-rows = nH
        mwait(Xm, phX & 1); phX++;
        accum_chunk<2, 128>(acc, sw1w + 640, K1, Xf, ks, c);
        fold_n(acc, sv);                                       // sv = nH (layer1)

        // now we need h0(t) from the whole group (latency covered by B4/B5)
        bar_wait(g_barA_gen, grp, genA + 1 + (unsigned)(t + 1));

        // B0 (Y), B1 (X): h0 chunks 0,1
        stage_bulk(Yu, h0w + 0 * (TB * 128) + gb * 128, 8192, Ym);
        stage_bulk(Xu, h0w + 1 * (TB * 128) + gb * 128, 8192, Xm);
        mwait(Ym, phY & 1); phY++;
        accum_chunk<2, 128>(acc, sw1w, K1, Yf, ks, c);         // n-rows = nI
        __syncthreads();
        stage_bulk(Yu, h0w + 2 * (TB * 128) + gb * 128, 8192, Ym);   // B2
        mwait(Xm, phX & 1); phX++;
        accum_chunk<2, 128>(acc, sw1w + 128, K1, Xf, ks, c);   // B1
        __syncthreads();
        stage_bulk(Xu, h0w + 3 * (TB * 128) + gb * 128, 8192, Xm);   // B3
        mwait(Ym, phY & 1); phY++;
        accum_chunk<2, 128>(acc, sw1w + 256, K1, Yf, ks, c);   // B2
        __syncthreads();
        if (t < TT - 1)                                        // A0(t+1) -> Y
            stage_bulk(Yu, g_xT + (t + 1) * (TB * TI) + gb * TI, 4096, Ym);
        mwait(Xm, phX & 1); phX++;
        accum_chunk<2, 128>(acc, sw1w + 384, K1, Xf, ks, c);   // B3
        reduce_layer<false>(acc, sv, warp, lane, GA, GB);
        __syncthreads();
        if (t < TT - 1)                                        // A1(t+1) -> X (h0r(t+1) = h0w(t) chunk 2d)
            stage_bulk(Xu, h0w + (2 * d) * (TB * 128) + gb * 128, 8192, Xm);
        {
            float aR  = GA[lu * BP + b] + b1r;
            float aZ  = GA[(16 + lu) * BP + b] + b1z;
            float aI  = GA[(32 + lu) * BP + b] + b1ni;
            float aH  = GB[lu * BP + b] + b1nh;
            float r  = sigmf(aR);
            float z  = sigmf(aZ);
            float n  = tanh_fast(aI + r * aH);
            float hn = n + z * (hp1 - n);
            __stcg(h1w + me_h, hn);
            if (t == myidx) out[(gb + b) * (2 * TH) + u] = hn;
        }

        // publish h1(t) (waited by the group at step t+1, fully covered)
        bar_arrive(g_barB_count, g_barB_gen, grp);

        // swap roles (pure register swaps)
        { float* tf = Xf; Xf = Yf; Yf = tf; }
        { unsigned tu = Xu; Xu = Yu; Yu = tu; }
        { unsigned tm = Xm; Xm = Ym; Ym = tm; }
        { int tp = phX; phX = phY; phY = tp; }
    }
}

// ---------------- launch ----------------
extern "C" void kernel_launch(void* const* d_in, const int* in_sizes, int n_in,
                              void* d_out, int out_size) {
    const float* x     = (const float*)d_in[0];
    const float* W_ih0 = (const float*)d_in[1];
    const float* W_hh0 = (const float*)d_in[2];
    const float* b_ih0 = (const float*)d_in[3];
    const float* b_hh0 = (const float*)d_in[4];
    const float* W_ih1 = (const float*)d_in[5];
    const float* W_hh1 = (const float*)d_in[6];
    const float* b_ih1 = (const float*)d_in[7];
    const float* b_hh1 = (const float*)d_in[8];
    const int*   seqlv = (const int*)d_in[9];
    float* out = (float*)d_out;

    const size_t SMEM_BYTES = (size_t)SMEM_FLOATS * sizeof(float);
    cudaFuncSetAttribute(gru_persistent, cudaFuncAttributeMaxDynamicSharedMemorySize,
                         (int)SMEM_BYTES);

    transpose_kernel<<<(TT * TB * TI + 255) / 256, 256>>>(x);
    gru_persistent<<<NCTA, NTHR, SMEM_BYTES>>>(W_ih0, W_hh0, b_ih0, b_hh0,
                                               W_ih1, W_hh1, b_ih1, b_hh1,
                                               seqlv, out);
}

// round 12
// speedup vs baseline: 1.0563x; 1.0563x over previous
#include <cuda_runtime.h>

// ---------------- problem constants ----------------
#define TB 64           // batch
#define TT 1024         // time steps
#define TI 64           // input size
#define TH 256          // hidden size
#define NGROUP 4        // independent batch groups
#define CPG 32          // CTAs per group
#define BPG 16          // batches per group
#define NCTA (NGROUP*CPG)
#define NTHR 256
#define K0 320          // layer0 concat [x(64) ; h0_d(256)]
#define K1 768          // layer1 concat [h0cat(512) ; h1_d(256)]
#define SXK 132         // smem x row stride (128 chunk + 4 pad)
#define BP  17          // gates buffer batch stride

// smem partition (floats)
#define OFS_SW0 0
#define OFS_SW1 (48*K0)                       // 15360
#define OFS_SX  (OFS_SW1 + 48*K1)             // 52224 : 2 buffers [16][SXK]
#define OFS_GA  (OFS_SX + 2*16*SXK)           // 56448 : [48 rows][BP]
#define OFS_GB  (OFS_GA + 48*BP)              // 57264 : [16 units][BP]
#define SMEM_FLOATS (OFS_GB + 16*BP)          // 57536 floats = 230144 bytes

// ---------------- device scratch ----------------
__device__ float g_xT[TT * TB * TI];          // [t][b][i]
__device__ float g_h0[2 * TB * 512];          // [parity][b][u]
__device__ float g_h1[2 * TB * 512];
__device__ int      g_barA_count[NGROUP];     // barrier A : h0 publish
__device__ unsigned g_barA_gen[NGROUP];
__device__ int      g_barB_count[NGROUP];     // barrier B : h1 publish
__device__ unsigned g_barB_gen[NGROUP];

// ---------------- input transpose ----------------
__global__ void transpose_kernel(const float* __restrict__ x) {
    int idx = blockIdx.x * blockDim.x + threadIdx.x;
    if (idx < TT * TB * TI) {
        int i = idx & 63;
        int b = (idx >> 6) & 63;
        int t = idx >> 12;
        g_xT[idx] = x[(b * TT + t) * TI + i];
    }
}

__device__ __forceinline__ float sigmf(float v) { return 1.0f / (1.0f + __expf(-v)); }
__device__ __forceinline__ float tanh_fast(float v) { return 2.0f / (1.0f + __expf(-2.0f * v)) - 1.0f; }

__device__ __forceinline__ void fma2(unsigned long long& acc,
                                     unsigned long long a, unsigned long long b) {
    asm("fma.rn.f32x2 %0, %1, %2, %0;" : "+l"(acc) : "l"(a), "l"(b));
}

// ---------------- cp.async helpers ----------------
__device__ __forceinline__ void cp16(float* s, const float* g) {
    unsigned ss = (unsigned)__cvta_generic_to_shared(s);
    asm volatile("cp.async.cg.shared.global [%0], [%1], 16;" :: "r"(ss), "l"(g) : "memory");
}
__device__ __forceinline__ void cp_commit() {
    asm volatile("cp.async.commit_group;" ::: "memory");
}
template <int N>
__device__ __forceinline__ void cp_wait() {
    asm volatile("cp.async.wait_group %0;" :: "n"(N) : "memory");
}

// stage CH floats per batch-row (16 rows) via cp.async
template <int CH>
__device__ __forceinline__ void stage_async(float* __restrict__ sx,
                                            const float* __restrict__ src, int srcStride) {
    constexpr int NV = CH / 4;
    for (int idx = threadIdx.x; idx < 16 * NV; idx += NTHR) {
        int bl = idx / NV;
        int kk = idx - bl * NV;
        cp16(sx + bl * SXK + kk * 4, src + bl * srcStride + kk * 4);
    }
    cp_commit();
}

// ---------------- split group barriers (proven atomic primitives) ----------------
__device__ __forceinline__ void bar_arrive(int* cnt, unsigned* gen, int grp) {
    __syncthreads();                          // all threads' global stores issued
    if (threadIdx.x == 0) {
        __threadfence();                      // release
        int prev = atomicAdd(&cnt[grp], 1);
        if (prev == CPG - 1) {
            atomicExch(&cnt[grp], 0);
            __threadfence();
            atomicAdd(&gen[grp], 1u);
        }
    }
}
__device__ __forceinline__ void bar_wait(unsigned* gen, int grp, unsigned target) {
    if (threadIdx.x == 0) {
        while (atomicAdd(&gen[grp], 0u) < target) { }
        __threadfence();                      // acquire
    }
    __syncthreads();
}

// split-K register-tiled accumulation.
// lane: ks = lane & 15 (16 k-slices), c = lane >> 4 (2 batch-octets).
// Lane tile: 6 rows x 8 batches x 4k. One j-iter covers 64 consecutive k.
// acc rows 0..3 = r/z rows (I+H merged), rows 4..5 = n rows.
template <int ITERS>
__device__ __forceinline__ void accum_chunk(unsigned long long acc[6][8],
                                            const float* __restrict__ wbase, int K,
                                            const float* __restrict__ sx,
                                            int ks, int c) {
    const float* xb = sx + (c * 8) * SXK;
#pragma unroll
    for (int j = 0; j < ITERS; ++j) {
        int k4 = (j * 16 + ks) * 4;
        ulonglong2 xv[8];
#pragma unroll
        for (int i = 0; i < 8; ++i)
            xv[i] = *reinterpret_cast<const ulonglong2*>(xb + i * SXK + k4);
        ulonglong2 wv[6];
#pragma unroll
        for (int r = 0; r < 6; ++r)
            wv[r] = *reinterpret_cast<const ulonglong2*>(wbase + r * K + k4);
#pragma unroll
        for (int r = 0; r < 6; ++r)
#pragma unroll
            for (int i = 0; i < 8; ++i) {
                fma2(acc[r][i], wv[r].x, xv[i].x);
                fma2(acc[r][i], wv[r].y, xv[i].y);
            }
    }
}

// fold n-rows (4,5) into sv and reset them (r/z rows keep running)
__device__ __forceinline__ void fold_n(unsigned long long acc[6][8], float sv[2][8]) {
#pragma unroll
    for (int q = 0; q < 2; ++q)
#pragma unroll
        for (int i = 0; i < 8; ++i) {
            union { unsigned long long u; float2 f; } cv; cv.u = acc[4 + q][i];
            sv[q][i] = cv.f.x + cv.f.y;
            acc[4 + q][i] = 0ull;
        }
}

// end-of-layer reduce. SAVED_IS_I: true -> sv is the n-gate INPUT part (layer0),
// false -> sv is the n-gate HIDDEN part (layer1, B4/B5 computed first).
template <bool SAVED_IS_I>
__device__ __forceinline__ void reduce_layer(unsigned long long acc[6][8],
                                             const float sv[2][8],
                                             int w, int lane,
                                             float* __restrict__ GA, float* __restrict__ GB) {
    const int c = lane >> 4;
    const bool wr = (lane & 15) == 0;
#pragma unroll
    for (int q = 0; q < 4; ++q) {              // r/z rows (total only)
        int garow = w * 4 + q;
#pragma unroll
        for (int i = 0; i < 8; ++i) {
            union { unsigned long long u; float2 f; } cv; cv.u = acc[q][i];
            float s = cv.f.x + cv.f.y;
            acc[q][i] = 0ull;
            s += __shfl_xor_sync(0xffffffffu, s, 1);
            s += __shfl_xor_sync(0xffffffffu, s, 2);
            s += __shfl_xor_sync(0xffffffffu, s, 4);
            s += __shfl_xor_sync(0xffffffffu, s, 8);
            if (wr) GA[garow * BP + c * 8 + i] = s;
        }
    }
#pragma unroll
    for (int q = 0; q < 2; ++q) {              // n rows
        int nn = w * 2 + q;
#pragma unroll
        for (int i = 0; i < 8; ++i) {
            union { unsigned long long u; float2 f; } cv; cv.u = acc[4 + q][i];
            float a = cv.f.x + cv.f.y;         // live accumulator part
            acc[4 + q][i] = 0ull;
            a += __shfl_xor_sync(0xffffffffu, a, 1);
            a += __shfl_xor_sync(0xffffffffu, a, 2);
            a += __shfl_xor_sync(0xffffffffu, a, 4);
            a += __shfl_xor_sync(0xffffffffu, a, 8);
            float s = sv[q][i];                // saved part
            s += __shfl_xor_sync(0xffffffffu, s, 1);
            s += __shfl_xor_sync(0xffffffffu, s, 2);
            s += __shfl_xor_sync(0xffffffffu, s, 4);
            s += __shfl_xor_sync(0xffffffffu, s, 8);
            if (wr) {
                if (SAVED_IS_I) {              // layer0: saved=I, rows=H
                    GA[(32 + nn) * BP + c * 8 + i] = s;
                    GB[nn * BP + c * 8 + i] = a;
                } else {                       // layer1: rows=I, saved=H
                    GA[(32 + nn) * BP + c * 8 + i] = a;
                    GB[nn * BP + c * 8 + i] = s;
                }
            }
        }
    }
}

// ---------------- persistent GRU kernel ----------------
__global__ void __launch_bounds__(NTHR, 1) gru_persistent(
    const float* __restrict__ W_ih0, const float* __restrict__ W_hh0,
    const float* __restrict__ b_ih0, const float* __restrict__ b_hh0,
    const float* __restrict__ W_ih1, const float* __restrict__ W_hh1,
    const float* __restrict__ b_ih1, const float* __restrict__ b_hh1,
    const int* __restrict__ seq_len, float* __restrict__ out)
{
    extern __shared__ float smem[];
    float* sw0 = smem + OFS_SW0;   // [48 warp-major rows][K0]
    float* sw1 = smem + OFS_SW1;   // [48][K1]
    float* sx0 = smem + OFS_SX;
    float* sx1 = smem + OFS_SX + 16 * SXK;
    float* GA  = smem + OFS_GA;    // [48][BP]  rows: r(0-15), z(16-31), nI(32-47)
    float* GB  = smem + OFS_GB;    // [16][BP]  nH

    const int tid = threadIdx.x;
    const int cta = blockIdx.x;
    const int grp = cta / CPG;
    const int cg  = cta % CPG;
    const int d     = cg >> 4;
    const int jbase = (cg & 15) * 16;
    const int gb    = grp * BPG;

    const int warp = tid >> 5;
    const int lane = tid & 31;
    const int ks   = lane & 15;
    const int c    = lane >> 4;

    const int lu = tid & 15;
    const int b  = tid >> 4;
    const int j  = jbase + lu;
    const int u  = d * TH + j;
    const int me = (gb + b) * 512 + u;

    // ---- stage weights into smem (warp-major rows: 4 r/z + 2 n per warp) ----
    for (int idx = tid; idx < 48 * K0; idx += NTHR) {
        int k = idx % K0, sr = idx / K0;
        int w = sr / 6, q = sr % 6;
        int gu;
        if (q < 4) { int rz = w * 4 + q; gu = (rz >> 4) * 256 + jbase + (rz & 15); }
        else       { int nn = w * 2 + (q - 4); gu = 512 + jbase + nn; }
        int grow = d * 768 + gu;
        sw0[idx] = (k < TI) ? W_ih0[grow * TI + k] : W_hh0[grow * TH + (k - TI)];
    }
    for (int idx = tid; idx < 48 * K1; idx += NTHR) {
        int k = idx % K1, sr = idx / K1;
        int w = sr / 6, q = sr % 6;
        int gu;
        if (q < 4) { int rz = w * 4 + q; gu = (rz >> 4) * 256 + jbase + (rz & 15); }
        else       { int nn = w * 2 + (q - 4); gu = 512 + jbase + nn; }
        int grow = d * 768 + gu;
        sw1[idx] = (k < 512) ? W_ih1[grow * 512 + k] : W_hh1[grow * TH + (k - 512)];
    }

    const int base = d * 768;
    const float b0r = b_ih0[base + j] + b_hh0[base + j];
    const float b0z = b_ih0[base + TH + j] + b_hh0[base + TH + j];
    const float b0ni = b_ih0[base + 2 * TH + j];
    const float b0nh = b_hh0[base + 2 * TH + j];
    const float b1r = b_ih1[base + j] + b_hh1[base + j];
    const float b1z = b_ih1[base + TH + j] + b_hh1[base + TH + j];
    const float b1ni = b_ih1[base + 2 * TH + j];
    const float b1nh = b_hh1[base + 2 * TH + j];

    int myidx = seq_len[gb + b] - 1;
    if (myidx < 0) myidx = 0;
    if (myidx > TT - 1) myidx = TT - 1;

    // zero initial hidden state (parity 0)
    __stcg(&g_h0[me], 0.0f);
    __stcg(&g_h1[me], 0.0f);

    __shared__ unsigned s_genA, s_genB;
    if (tid == 0) {
        s_genA = atomicAdd(&g_barA_gen[grp], 0u);
        s_genB = atomicAdd(&g_barB_gen[grp], 0u);
    }
    __syncthreads();
    const unsigned genA = s_genA;
    const unsigned genB = s_genB;

    // prologue: barB arrive = "h1(-1) zeros published";
    // barA full barrier makes h0 zeros (and weights ordering) group-visible.
    bar_arrive(g_barB_count, g_barB_gen, grp);
    bar_arrive(g_barA_count, g_barA_gen, grp);
    bar_wait(g_barA_gen, grp, genA + 1);

    unsigned long long acc[6][8];
#pragma unroll
    for (int r = 0; r < 6; ++r)
#pragma unroll
        for (int i = 0; i < 8; ++i) acc[r][i] = 0ull;

    const float* sw0w = sw0 + warp * 6 * K0;
    const float* sw1w = sw1 + warp * 6 * K1;

    // prologue staging: A0(0) -> sx0, A1(0) -> sx1
    stage_async<64>(sx0, g_xT + gb * TI, TI);
    stage_async<128>(sx1, g_h0 + gb * 512 + d * TH, 512);

    for (int t = 0; t < TT; ++t) {
        const int rp = t & 1, wp = rp ^ 1;
        const float* h0r = g_h0 + rp * (TB * 512);
        float*       h0w = g_h0 + wp * (TB * 512);
        const float* h1r = g_h1 + rp * (TB * 512);
        float*       h1w = g_h1 + wp * (TB * 512);
        float* bA = (t & 1) ? sx1 : sx0;   // slots A0,A2,B5,B1,B3,A1'
        float* bB = (t & 1) ? sx0 : sx1;   // slots A1,B4,B0,B2,A0'

        float sv[2][8];

        // ================= phase 1 : layer 0  (K = 64 + 256) =================
        float hp0 = __ldcg(h0r + me);      // own thread's prior write
        float hp1 = __ldcg(h1r + me);

        // slot A0 (bA): x part            outstanding: [A0, A1]
        cp_wait<1>(); __syncthreads();
        accum_chunk<1>(acc, sw0w, K0, bA, ks, c);
        fold_n(acc, sv);                                    // sv = nI (layer0)
        __syncthreads();
        stage_async<128>(bA, h0r + gb * 512 + d * TH + 128, 512);   // A2
        // slot A1 (bB): h0_d k 0..127     outstanding: [A1, A2]
        cp_wait<1>(); __syncthreads();
        accum_chunk<2>(acc, sw0w + TI, K0, bB, ks, c);
        // slot A2 (bA): h0_d k 128..255
        cp_wait<0>(); __syncthreads();
        accum_chunk<2>(acc, sw0w + TI + 128, K0, bA, ks, c);
        reduce_layer<true>(acc, sv, warp, lane, GA, GB);
        __syncthreads();
        {
            float aR  = GA[lu * BP + b] + b0r;
            float aZ  = GA[(16 + lu) * BP + b] + b0z;
            float aI  = GA[(32 + lu) * BP + b] + b0ni;
            float aH  = GB[lu * BP + b] + b0nh;
            float r  = sigmf(aR);
            float z  = sigmf(aZ);
            float n  = tanh_fast(aI + r * aH);
            float hn = n + z * (hp0 - n);
            __stcg(h0w + me, hn);
        }

        // publish h0(t); wait deferred past the h1-hidden part
        bar_arrive(g_barA_count, g_barA_gen, grp);

        // h1(t-1) must be globally published before B4/B5 read it; barB was
        // arrived at the END of step t-1 (prologue for t=0) — latency covered
        // by all of phase 1.
        bar_wait(g_barB_gen, grp, genB + 1 + (unsigned)t);

        // ================= phase 2 : layer 1  (K = 512 + 256) =================
        // B4 (bB), B5 (bA): h1_d chunks first (pre-barA-wait work)
        stage_async<128>(bB, h1r + gb * 512 + d * TH, 512);         // B4
        stage_async<128>(bA, h1r + gb * 512 + d * TH + 128, 512);   // B5
        cp_wait<1>(); __syncthreads();
        accum_chunk<2>(acc, sw1w + 512, K1, bB, ks, c);             // B4 (n-rows = nH)
        cp_wait<0>(); __syncthreads();
        accum_chunk<2>(acc, sw1w + 640, K1, bA, ks, c);             // B5
        fold_n(acc, sv);                                            // sv = nH (layer1)

        // now we need h0(t) from the whole group (latency covered by B4/B5)
        bar_wait(g_barA_gen, grp, genA + 2 + (unsigned)t);

        // B0 (bB), B1 (bA): h0 chunks 0,1
        stage_async<128>(bB, h0w + gb * 512 + 0,   512);            // B0
        stage_async<128>(bA, h0w + gb * 512 + 128, 512);            // B1
        cp_wait<1>(); __syncthreads();
        accum_chunk<2>(acc, sw1w, K1, bB, ks, c);                   // B0 (n-rows = nI)
        __syncthreads();
        stage_async<128>(bB, h0w + gb * 512 + 256, 512);            // B2
        cp_wait<1>(); __syncthreads();
        accum_chunk<2>(acc, sw1w + 128, K1, bA, ks, c);             // B1
        __syncthreads();
        stage_async<128>(bA, h0w + gb * 512 + 384, 512);            // B3
        cp_wait<1>(); __syncthreads();
        accum_chunk<2>(acc, sw1w + 256, K1, bB, ks, c);             // B2
        __syncthreads();
        {   // A0(t+1) -> bB : x prefetch (clamped at sequence end)
            int tt = (t + 1 < TT) ? t + 1 : TT - 1;
            stage_async<64>(bB, g_xT + tt * (TB * TI) + gb * TI, TI);
        }
        cp_wait<1>(); __syncthreads();
        accum_chunk<2>(acc, sw1w + 384, K1, bA, ks, c);             // B3
        reduce_layer<false>(acc, sv, warp, lane, GA, GB);
        __syncthreads();
        stage_async<128>(bA, h0w + gb * 512 + d * TH, 512);         // A1(t+1)
        {
            float aR  = GA[lu * BP + b] + b1r;
            float aZ  = GA[(16 + lu) * BP + b] + b1z;
            float aI  = GA[(32 + lu) * BP + b] + b1ni;
            float aH  = GB[lu * BP + b] + b1nh;
            float r  = sigmf(aR);
            float z  = sigmf(aZ);
            float n  = tanh_fast(aI + r * aH);
            float hn = n + z * (hp1 - n);
            __stcg(h1w + me, hn);
            if (t == myidx) out[(gb + b) * (2 * TH) + u] = hn;
        }

        // publish h1(t) (waited by the group at step t+1, fully covered)
        bar_arrive(g_barB_count, g_barB_gen, grp);
    }

    cp_wait<0>();      // drain the speculative t=TT stages
    __syncthreads();
}

// ---------------- launch ----------------
extern "C" void kernel_launch(void* const* d_in, const int* in_sizes, int n_in,
                              void* d_out, int out_size) {
    const float* x     = (const float*)d_in[0];
    const float* W_ih0 = (const float*)d_in[1];
    const float* W_hh0 = (const float*)d_in[2];
    const float* b_ih0 = (const float*)d_in[3];
    const float* b_hh0 = (const float*)d_in[4];
    const float* W_ih1 = (const float*)d_in[5];
    const float* W_hh1 = (const float*)d_in[6];
    const float* b_ih1 = (const float*)d_in[7];
    const float* b_hh1 = (const float*)d_in[8];
    const int*   seqlv = (const int*)d_in[9];
    float* out = (float*)d_out;

    const size_t SMEM_BYTES = (size_t)SMEM_FLOATS * sizeof(float);
    cudaFuncSetAttribute(gru_persistent, cudaFuncAttributeMaxDynamicSharedMemorySize,
                         (int)SMEM_BYTES);

    transpose_kernel<<<(TT * TB * TI + 255) / 256, 256>>>(x);
    gru_persistent<<<NCTA, NTHR, SMEM_BYTES>>>(W_ih0, W_hh0, b_ih0, b_hh0,
                                               W_ih1, W_hh1, b_ih1, b_hh1,
                                               seqlv, out);
}

// round 13
// speedup vs baseline: 1.1285x; 1.0683x over previous
#include <cuda_runtime.h>

// ---------------- problem constants ----------------
#define TB 64           // batch
#define TT 1024         // time steps
#define TI 64           // input size
#define TH 256          // hidden size
#define NGROUP 4        // independent batch groups
#define CPG 32          // CTAs per group
#define BPG 16          // batches per group
#define NCTA (NGROUP*CPG)
#define NTHR 256
#define K0 320          // layer0 concat [x(64) ; h0_d(256)]
#define K1 768          // layer1 concat [h0cat(512) ; h1_d(256)]
#define XS  128         // smem staging row stride (floats, unpadded - proven conflict-free)
#define BP  17          // gates buffer batch stride

// smem partition (floats)
#define OFS_SW0 0                             // 48*320 = 15360
#define OFS_SW1 (48*K0)                       // 15360 : 48*768 = 36864
#define OFS_B0  (OFS_SW1 + 48*K1)             // 52224 : big buffer 0 [16][128]
#define OFS_B1  (OFS_B0 + 2048)               // 54272 : big buffer 1
#define OFS_GA  (OFS_B1 + 2048)               // 56320 : [48 rows][BP]
#define OFS_GB  (OFS_GA + 48*BP)              // 57136 : [16][BP]
#define SMEM_FLOATS (OFS_GB + 16*BP)          // 57408 floats = 229632 bytes (fits 227KB)

// ---------------- device scratch ----------------
__device__ float g_xT[TT * TB * TI];          // [t][b][i]
__device__ float g_h0[2 * TB * 512];          // [parity][b][u]
__device__ float g_h1[2 * TB * 512];
__device__ int      g_barA_count[NGROUP];     // barrier A : h0 publish
__device__ unsigned g_barA_gen[NGROUP];
__device__ int      g_barB_count[NGROUP];     // barrier B : h1 publish
__device__ unsigned g_barB_gen[NGROUP];

// ---------------- input transpose ----------------
__global__ void transpose_kernel(const float* __restrict__ x) {
    int idx = blockIdx.x * blockDim.x + threadIdx.x;
    if (idx < TT * TB * TI) {
        int i = idx & 63;
        int b = (idx >> 6) & 63;
        int t = idx >> 12;
        g_xT[idx] = x[(b * TT + t) * TI + i];
    }
}

__device__ __forceinline__ float sigmf(float v) { return 1.0f / (1.0f + __expf(-v)); }
__device__ __forceinline__ float tanh_fast(float v) { return 2.0f / (1.0f + __expf(-2.0f * v)) - 1.0f; }

__device__ __forceinline__ void fma2(unsigned long long& acc,
                                     unsigned long long a, unsigned long long b) {
    asm("fma.rn.f32x2 %0, %1, %2, %0;" : "+l"(acc) : "l"(a), "l"(b));
}

// ---------------- cp.async helpers ----------------
__device__ __forceinline__ void cp16(float* s, const float* g) {
    unsigned ss = (unsigned)__cvta_generic_to_shared(s);
    asm volatile("cp.async.cg.shared.global [%0], [%1], 16;" :: "r"(ss), "l"(g) : "memory");
}
__device__ __forceinline__ void cp_commit() {
    asm volatile("cp.async.commit_group;" ::: "memory");
}
template <int N>
__device__ __forceinline__ void cp_wait() {
    asm volatile("cp.async.wait_group %0;" :: "n"(N) : "memory");
}

// stage 128 floats per batch-row (16 rows) via cp.async  (one commit group)
__device__ __forceinline__ void stage128(float* __restrict__ sx,
                                         const float* __restrict__ src, int srcStride) {
    for (int idx = threadIdx.x; idx < 16 * 32; idx += NTHR) {
        int bl = idx >> 5;
        int kk = idx & 31;
        cp16(sx + bl * XS + kk * 4, src + bl * srcStride + kk * 4);
    }
    cp_commit();
}

// ---------------- split group barriers (proven atomic primitives) ----------------
__device__ __forceinline__ void bar_arrive(int* cnt, unsigned* gen, int grp) {
    __syncthreads();                          // all threads' stores issued / smem reads done
    if (threadIdx.x == 0) {
        __threadfence();                      // release
        int prev = atomicAdd(&cnt[grp], 1);
        if (prev == CPG - 1) {
            atomicExch(&cnt[grp], 0);
            __threadfence();
            atomicAdd(&gen[grp], 1u);
        }
    }
}
__device__ __forceinline__ void bar_wait(unsigned* gen, int grp, unsigned target) {
    if (threadIdx.x == 0) {
        while (atomicAdd(&gen[grp], 0u) < target) { }
        __threadfence();                      // acquire
    }
    __syncthreads();
}

// split-K register-tiled accumulation (6 rows x 4 batches per lane tile).
// lane: ks = lane & 7 (8 k-slices), c = lane >> 3 (4 batch-quads).
// One j-iter covers 32 consecutive k; ITERS = chunk/32.
// Conflict-free: each 8-lane LDS phase reads 8 consecutive 16B (128B, all banks).
template <int ITERS>
__device__ __forceinline__ void accum_chunk(unsigned long long acc[6][4],
                                            const float* __restrict__ wbase, int K,
                                            const float* __restrict__ sx,
                                            int ks, int c) {
    const float* xb = sx + (c * 4) * XS;
#pragma unroll
    for (int j = 0; j < ITERS; ++j) {
        int k4 = (j * 8 + ks) * 4;
        ulonglong2 xv[4];
#pragma unroll
        for (int i = 0; i < 4; ++i)
            xv[i] = *reinterpret_cast<const ulonglong2*>(xb + i * XS + k4);
        ulonglong2 wv[6];
#pragma unroll
        for (int r = 0; r < 6; ++r)
            wv[r] = *reinterpret_cast<const ulonglong2*>(wbase + r * K + k4);
#pragma unroll
        for (int r = 0; r < 6; ++r)
#pragma unroll
            for (int i = 0; i < 4; ++i) {
                fma2(acc[r][i], wv[r].x, xv[i].x);
                fma2(acc[r][i], wv[r].y, xv[i].y);
            }
    }
}

// layer-0 x part: xv held in REGISTERS (xr[j*4+i]), weights from smem x-part.
__device__ __forceinline__ void accum_x(unsigned long long acc[6][4],
                                        const float* __restrict__ sw0w,
                                        const ulonglong2 xr[8], int ks) {
#pragma unroll
    for (int j = 0; j < 2; ++j) {
        int k4 = (j * 8 + ks) * 4;
        ulonglong2 wv[6];
#pragma unroll
        for (int r = 0; r < 6; ++r)
            wv[r] = *reinterpret_cast<const ulonglong2*>(sw0w + r * K0 + k4);
#pragma unroll
        for (int r = 0; r < 6; ++r)
#pragma unroll
            for (int i = 0; i < 4; ++i) {
                fma2(acc[r][i], wv[r].x, xr[j * 4 + i].x);
                fma2(acc[r][i], wv[r].y, xr[j * 4 + i].y);
            }
    }
}

// fold n-rows (4,5) into sv and reset them (r/z rows keep running)
__device__ __forceinline__ void fold_n(unsigned long long acc[6][4], float sv[2][4]) {
#pragma unroll
    for (int q = 0; q < 2; ++q)
#pragma unroll
        for (int i = 0; i < 4; ++i) {
            union { unsigned long long u; float2 f; } cv; cv.u = acc[4 + q][i];
            sv[q][i] = cv.f.x + cv.f.y;
            acc[4 + q][i] = 0ull;
        }
}

// end-of-layer reduce: live n-rows = I part, sv = H part (both layers use this
// convention: hidden part accumulated first, folded, then input part).
__device__ __forceinline__ void reduce_layer(unsigned long long acc[6][4],
                                             const float sv[2][4],
                                             int w, int lane,
                                             float* __restrict__ GA, float* __restrict__ GB) {
    const int c = lane >> 3;
    const bool wr = (lane & 7) == 0;
#pragma unroll
    for (int q = 0; q < 4; ++q) {              // r/z rows (total only)
        int garow = w * 4 + q;
#pragma unroll
        for (int i = 0; i < 4; ++i) {
            union { unsigned long long u; float2 f; } cv; cv.u = acc[q][i];
            float s = cv.f.x + cv.f.y;
            acc[q][i] = 0ull;
            s += __shfl_xor_sync(0xffffffffu, s, 1);
            s += __shfl_xor_sync(0xffffffffu, s, 2);
            s += __shfl_xor_sync(0xffffffffu, s, 4);
            if (wr) GA[garow * BP + c * 4 + i] = s;
        }
    }
#pragma unroll
    for (int q = 0; q < 2; ++q) {              // n rows
        int nn = w * 2 + q;
#pragma unroll
        for (int i = 0; i < 4; ++i) {
            union { unsigned long long u; float2 f; } cv; cv.u = acc[4 + q][i];
            float a = cv.f.x + cv.f.y;         // live = I part
            acc[4 + q][i] = 0ull;
            a += __shfl_xor_sync(0xffffffffu, a, 1);
            a += __shfl_xor_sync(0xffffffffu, a, 2);
            a += __shfl_xor_sync(0xffffffffu, a, 4);
            float s = sv[q][i];                // saved = H part
            s += __shfl_xor_sync(0xffffffffu, s, 1);
            s += __shfl_xor_sync(0xffffffffu, s, 2);
            s += __shfl_xor_sync(0xffffffffu, s, 4);
            if (wr) {
                GA[(32 + nn) * BP + c * 4 + i] = a;
                GB[nn * BP + c * 4 + i] = s;
            }
        }
    }
}

// ---------------- persistent GRU kernel ----------------
__global__ void __launch_bounds__(NTHR, 1) gru_persistent(
    const float* __restrict__ W_ih0, const float* __restrict__ W_hh0,
    const float* __restrict__ b_ih0, const float* __restrict__ b_hh0,
    const float* __restrict__ W_ih1, const float* __restrict__ W_hh1,
    const float* __restrict__ b_ih1, const float* __restrict__ b_hh1,
    const int* __restrict__ seq_len, float* __restrict__ out)
{
    extern __shared__ float smem[];
    float* sw0 = smem + OFS_SW0;   // [48 warp-major rows][K0]
    float* sw1 = smem + OFS_SW1;   // [48][K1]
    float* big0 = smem + OFS_B0;   // [16][128]
    float* big1 = smem + OFS_B1;   // [16][128]
    float* GA  = smem + OFS_GA;    // [48][BP]  rows: r(0-15), z(16-31), nI(32-47)
    float* GB  = smem + OFS_GB;    // [16][BP]  nH

    const int tid = threadIdx.x;
    const int cta = blockIdx.x;
    const int grp = cta / CPG;
    const int cg  = cta % CPG;
    const int d     = cg >> 4;
    const int jbase = (cg & 15) * 16;
    const int gb    = grp * BPG;

    const int warp = tid >> 5;
    const int lane = tid & 31;
    const int ks   = lane & 7;
    const int c    = lane >> 3;

    const int lu = tid & 15;
    const int b  = tid >> 4;
    const int j  = jbase + lu;
    const int u  = d * TH + j;
    const int me = (gb + b) * 512 + u;

    // ---- stage weights into smem (warp-major rows: 4 r/z + 2 n per warp) ----
    for (int idx = tid; idx < 48 * K0; idx += NTHR) {
        int k = idx % K0, sr = idx / K0;
        int w = sr / 6, q = sr % 6;
        int gu;
        if (q < 4) { int rz = w * 4 + q; gu = (rz >> 4) * 256 + jbase + (rz & 15); }
        else       { int nn = w * 2 + (q - 4); gu = 512 + jbase + nn; }
        int grow = d * 768 + gu;
        sw0[idx] = (k < TI) ? W_ih0[grow * TI + k] : W_hh0[grow * TH + (k - TI)];
    }
    for (int idx = tid; idx < 48 * K1; idx += NTHR) {
        int k = idx % K1, sr = idx / K1;
        int w = sr / 6, q = sr % 6;
        int gu;
        if (q < 4) { int rz = w * 4 + q; gu = (rz >> 4) * 256 + jbase + (rz & 15); }
        else       { int nn = w * 2 + (q - 4); gu = 512 + jbase + nn; }
        int grow = d * 768 + gu;
        sw1[idx] = (k < 512) ? W_ih1[grow * 512 + k] : W_hh1[grow * TH + (k - 512)];
    }

    const int base = d * 768;
    const float b0r = b_ih0[base + j] + b_hh0[base + j];
    const float b0z = b_ih0[base + TH + j] + b_hh0[base + TH + j];
    const float b0ni = b_ih0[base + 2 * TH + j];
    const float b0nh = b_hh0[base + 2 * TH + j];
    const float b1r = b_ih1[base + j] + b_hh1[base + j];
    const float b1z = b_ih1[base + TH + j] + b_hh1[base + TH + j];
    const float b1ni = b_ih1[base + 2 * TH + j];
    const float b1nh = b_hh1[base + 2 * TH + j];

    int myidx = seq_len[gb + b] - 1;
    if (myidx < 0) myidx = 0;
    if (myidx > TT - 1) myidx = TT - 1;

    // zero initial hidden state (parity 0)
    __stcg(&g_h0[me], 0.0f);
    __stcg(&g_h1[me], 0.0f);

    __shared__ unsigned s_genA, s_genB;
    if (tid == 0) {
        s_genA = atomicAdd(&g_barA_gen[grp], 0u);
        s_genB = atomicAdd(&g_barB_gen[grp], 0u);
    }
    __syncthreads();
    const unsigned genA = s_genA;
    const unsigned genB = s_genB;

    // prologue: barB arrive = "h1(-1) zeros published";
    // barA full barrier makes h0 zeros group-visible.
    bar_arrive(g_barB_count, g_barB_gen, grp);
    bar_arrive(g_barA_count, g_barA_gen, grp);
    bar_wait(g_barA_gen, grp, genA + 1);

    unsigned long long acc[6][4];
#pragma unroll
    for (int r = 0; r < 6; ++r)
#pragma unroll
        for (int i = 0; i < 4; ++i) acc[r][i] = 0ull;

    const float* sw0w = sw0 + warp * 6 * K0;
    const float* sw1w = sw1 + warp * 6 * K1;

    // prologue staging: A1(0) -> big0, A2(0) -> big1  (h0 parity0 zeros)
    stage128(big0, g_h0 + gb * 512 + d * TH, 512);
    stage128(big1, g_h0 + gb * 512 + d * TH + 128, 512);

    for (int t = 0; t < TT; ++t) {
        const int rp = t & 1, wp = rp ^ 1;
        const float* h0r = g_h0 + rp * (TB * 512);
        float*       h0w = g_h0 + wp * (TB * 512);
        const float* h1r = g_h1 + rp * (TB * 512);
        float*       h1w = g_h1 + wp * (TB * 512);

        float sv[2][4];

        // --- step top: own h values + x prefetch into registers ---
        float hp0 = __ldcg(h0r + me);
        float hp1 = __ldcg(h1r + me);
        ulonglong2 xr[8];
        {
            const float* xbase = g_xT + t * (TB * TI) + gb * TI;
#pragma unroll
            for (int jj = 0; jj < 2; ++jj)
#pragma unroll
                for (int i = 0; i < 4; ++i)
                    xr[jj * 4 + i] = __ldcg(reinterpret_cast<const ulonglong2*>(
                        xbase + (c * 4 + i) * TI + (jj * 8 + ks) * 4));
        }

        // ================= phase 1 : layer 0 =================
        // A1 (big0): h0_d k 0..127        outstanding [A1, A2]
        cp_wait<1>(); __syncthreads();
        accum_chunk<4>(acc, sw0w + TI, K0, big0, ks, c);

        // h1(t-1) globally published (arrived at end of step t-1; cover = A1)
        bar_wait(g_barB_gen, grp, genB + 1 + (unsigned)t);
        stage128(big0, h1r + gb * 512 + d * TH, 512);              // B4

        // A2 (big1): h0_d k 128..255      outstanding [A2, B4]
        cp_wait<1>(); __syncthreads();
        accum_chunk<4>(acc, sw0w + TI + 128, K0, big1, ks, c);
        fold_n(acc, sv);                                           // sv = nH (layer0)
        accum_x(acc, sw0w, xr, ks);                                // x part (n-rows = nI)
        reduce_layer(acc, sv, warp, lane, GA, GB);
        __syncthreads();
        {
            float aR  = GA[lu * BP + b] + b0r;
            float aZ  = GA[(16 + lu) * BP + b] + b0z;
            float aI  = GA[(32 + lu) * BP + b] + b0ni;
            float aH  = GB[lu * BP + b] + b0nh;
            float r  = sigmf(aR);
            float z  = sigmf(aZ);
            float n  = tanh_fast(aI + r * aH);
            float hn = n + z * (hp0 - n);
            __stcg(h0w + me, hn);
        }

        // publish h0(t); wait deferred past B4/B5
        bar_arrive(g_barA_count, g_barA_gen, grp);
        stage128(big1, h1r + gb * 512 + d * TH + 128, 512);        // B5

        // ================= phase 2 : layer 1 =================
        // B4 (big0)                        outstanding [B4, B5]
        cp_wait<1>(); __syncthreads();
        accum_chunk<4>(acc, sw1w + 512, K1, big0, ks, c);
        // B5 (big1)
        cp_wait<0>(); __syncthreads();
        accum_chunk<4>(acc, sw1w + 640, K1, big1, ks, c);
        fold_n(acc, sv);                                           // sv = nH (layer1)

        // h0(t) from the whole group (cover = B4+B5)
        bar_wait(g_barA_gen, grp, genA + 2 + (unsigned)t);
        stage128(big0, h0w + gb * 512 + 0,   512);                 // B0
        stage128(big1, h0w + gb * 512 + 128, 512);                 // B1

        // B0 (big0)                        outstanding [B0, B1]
        cp_wait<1>(); __syncthreads();
        accum_chunk<4>(acc, sw1w, K1, big0, ks, c);
        __syncthreads();
        stage128(big0, h0w + gb * 512 + 256, 512);                 // B2
        // B1 (big1)                        outstanding [B1, B2]
        cp_wait<1>(); __syncthreads();
        accum_chunk<4>(acc, sw1w + 128, K1, big1, ks, c);
        __syncthreads();
        stage128(big1, h0w + gb * 512 + 384, 512);                 // B3
        // B2 (big0)                        outstanding [B2, B3]
        cp_wait<1>(); __syncthreads();
        accum_chunk<4>(acc, sw1w + 256, K1, big0, ks, c);
        __syncthreads();
        stage128(big0, h0w + gb * 512 + d * TH, 512);              // A1(t+1) = h0r(t+1) chunk
        // B3 (big1)                        outstanding [B3, A1']
        cp_wait<1>(); __syncthreads();
        accum_chunk<4>(acc, sw1w + 384, K1, big1, ks, c);
        reduce_layer(acc, sv, warp, lane, GA, GB);
        __syncthreads();
        {
            float aR  = GA[lu * BP + b] + b1r;
            float aZ  = GA[(16 + lu) * BP + b] + b1z;
            float aI  = GA[(32 + lu) * BP + b] + b1ni;
            float aH  = GB[lu * BP + b] + b1nh;
            float r  = sigmf(aR);
            float z  = sigmf(aZ);
            float n  = tanh_fast(aI + r * aH);
            float hn = n + z * (hp1 - n);
            __stcg(h1w + me, hn);
            if (t == myidx) out[(gb + b) * (2 * TH) + u] = hn;
        }

        // publish h1(t); its entry syncthreads also frees big1 for A2'
        bar_arrive(g_barB_count, g_barB_gen, grp);
        stage128(big1, h0w + gb * 512 + d * TH + 128, 512);        // A2(t+1)
    }

    cp_wait<0>();      // drain the final speculative stages
    __syncthreads();
}

// ---------------- launch ----------------
extern "C" void kernel_launch(void* const* d_in, const int* in_sizes, int n_in,
                              void* d_out, int out_size) {
    const float* x     = (const float*)d_in[0];
    const float* W_ih0 = (const float*)d_in[1];
    const float* W_hh0 = (const float*)d_in[2];
    const float* b_ih0 = (const float*)d_in[3];
    const float* b_hh0 = (const float*)d_in[4];
    const float* W_ih1 = (const float*)d_in[5];
    const float* W_hh1 = (const float*)d_in[6];
    const float* b_ih1 = (const float*)d_in[7];
    const float* b_hh1 = (const float*)d_in[8];
    const int*   seqlv = (const int*)d_in[9];
    float* out = (float*)d_out;

    const size_t SMEM_BYTES = (size_t)SMEM_FLOATS * sizeof(float);
    cudaFuncSetAttribute(gru_persistent, cudaFuncAttributeMaxDynamicSharedMemorySize,
                         (int)SMEM_BYTES);

    transpose_kernel<<<(TT * TB * TI + 255) / 256, 256>>>(x);
    gru_persistent<<<NCTA, NTHR, SMEM_BYTES>>>(W_ih0, W_hh0, b_ih0, b_hh0,
                                               W_ih1, W_hh1, b_ih1, b_hh1,
                                               seqlv, out);
}